// round 1
// baseline (speedup 1.0000x reference)
#include <cuda_runtime.h>
#include <cstdint>

// Problem constants
#define S_LEN 4096
#define D 2048
#define NT 32000
#define INP 4097          // D + D + 1
#define N_NODES 4097      // S_LEN + 1

// ---------------- scratch (device globals; no allocation) ----------------
__device__ float g_part_cs[32 * D];     // column-sum partials
__device__ float g_vecA[D];             // s (colsum), then v2
__device__ float g_vecB[D];             // m (mean msg)
__device__ float g_part[16 * D];        // left-matvec partials
__device__ float g_inp[INP];            // LSTM input vector
__device__ float g_gsum[4 * D];         // gate pre-activations
__device__ float g_newh[D];             // new hidden
__device__ float g_pout[16 * NT];       // output matvec partials (2 MB)

// ---------------- kernels ----------------

// Column sum of hiddens [S_LEN, D] -> partials [32][D]
__global__ void k_colsum_partial(const float* __restrict__ hid) {
    int col = blockIdx.x * 256 + threadIdx.x;        // gridDim.x = 8
    int r0  = blockIdx.y * (S_LEN / 32);             // gridDim.y = 32, 128 rows each
    float acc = 0.f;
    #pragma unroll 8
    for (int r = 0; r < S_LEN / 32; ++r)
        acc += hid[(r0 + r) * D + col];
    g_part_cs[blockIdx.y * D + col] = acc;
}

__global__ void k_colsum_reduce() {
    int col = blockIdx.x * 256 + threadIdx.x;
    float a = 0.f;
    #pragma unroll
    for (int k = 0; k < 32; ++k) a += g_part_cs[k * D + col];
    g_vecA[col] = a;
}

// Left matvec partials: part[ks][col] = sum_{k in chunk} v[k] * W[k*D + col]
__global__ void k_lmv_partial(const float* __restrict__ v, const float* __restrict__ W) {
    int col = blockIdx.x * 256 + threadIdx.x;        // gridDim.x = 8
    int k0  = blockIdx.y * (D / 16);                 // gridDim.y = 16, 128 rows each
    float acc = 0.f;
    #pragma unroll 8
    for (int k = 0; k < D / 16; ++k)
        acc += v[k0 + k] * W[(k0 + k) * D + col];
    g_part[blockIdx.y * D + col] = acc;
}

// Reduce partials with optional add-vector, scale, relu.
__global__ void k_lmv_reduce(float* __restrict__ out, const float* __restrict__ addvec,
                             float scale, int do_relu) {
    int col = blockIdx.x * 256 + threadIdx.x;
    float a = 0.f;
    #pragma unroll
    for (int k = 0; k < 16; ++k) a += g_part[k * D + col];
    if (addvec) a += addvec[col];
    a *= scale;
    if (do_relu) a = fmaxf(a, 0.f);
    out[col] = a;
}

// Fill g_inp[0:D) = sen_emb, g_inp[2D] = pos_index (dtype-defensive).
__global__ void k_prep_inp(const float* __restrict__ sen, const int* __restrict__ pos_raw) {
    int i = blockIdx.x * 256 + threadIdx.x;
    g_inp[i] = sen[i];
    if (i == 0) {
        int bits = pos_raw[0];
        float f;
        if (bits >= 0 && bits < 1000000) f = (float)bits;   // stored as int32/int64-lo
        else f = __int_as_float(bits);                      // stored as float32
        g_inp[2 * D] = f;
    }
}

// Gate pre-activations: one warp per (gate,row). gsum = Wi.inp + Wh.curh + bi + bh
__global__ void k_gsum(const float* __restrict__ Wi, const float* __restrict__ Wh,
                       const float* __restrict__ bi, const float* __restrict__ bh,
                       const float* __restrict__ curh) {
    int warp = (blockIdx.x * blockDim.x + threadIdx.x) >> 5;   // [0, 8192)
    int lane = threadIdx.x & 31;
    const float* wi_row = Wi + (long)warp * INP;
    const float* wh_row = Wh + (long)warp * D;
    float acc = 0.f;
    #pragma unroll 8
    for (int i = lane; i < INP; i += 32) acc += wi_row[i] * g_inp[i];
    #pragma unroll 8
    for (int i = lane; i < D; i += 32) acc += wh_row[i] * curh[i];
    #pragma unroll
    for (int o = 16; o; o >>= 1) acc += __shfl_down_sync(0xffffffffu, acc, o);
    if (lane == 0) g_gsum[warp] = acc + bi[warp] + bh[warp];
}

__device__ __forceinline__ float sigf(float x) { return 1.f / (1.f + expf(-x)); }

__global__ void k_gates(const float* __restrict__ cur_cell) {
    int h = blockIdx.x * 256 + threadIdx.x;
    float i_g = sigf(g_gsum[h]);
    float f_g = sigf(g_gsum[D + h]);
    float g_g = tanhf(g_gsum[2 * D + h]);
    float o_g = sigf(g_gsum[3 * D + h]);
    float nc  = f_g * cur_cell[h] + i_g * g_g;
    g_newh[h] = o_g * tanhf(nc);
}

// Output matvec partials: new_h (D) x dim_out [D, NT]
__global__ void k_out_partial(const float* __restrict__ Wout) {
    int n  = blockIdx.x * 256 + threadIdx.x;         // gridDim.x = 125 -> 32000
    int k0 = blockIdx.y * (D / 16);                  // gridDim.y = 16, 128 rows each
    float acc = 0.f;
    #pragma unroll 8
    for (int k = 0; k < D / 16; ++k)
        acc += g_newh[k0 + k] * Wout[(long)(k0 + k) * NT + n];
    g_pout[blockIdx.y * NT + n] = acc;
}

__global__ void k_out_reduce(float* __restrict__ out) {
    int n = blockIdx.x * 256 + threadIdx.x;
    float a = 0.f;
    #pragma unroll
    for (int k = 0; k < 16; ++k) a += g_pout[k * NT + n];
    out[n] = a;
}

// ---------------- launcher ----------------
// Input order (reference setup_inputs):
// 0 sen_emb [D], 1 hiddens [S,D], 2 pos_index [1], 3 dim_up [D,D], 4 dim_down [D,D],
// 5 dim_out [D,NT], 6 W_gcn [D,D], 7 att_w [D] (unused: attention is exactly uniform),
// 8 Wi [4,D,INP], 9 Wh [4,D,D], 10 bi [4,D], 11 bh [4,D], 12 cur_h [D], 13 cur_cell [D]
extern "C" void kernel_launch(void* const* d_in, const int* in_sizes, int n_in,
                              void* d_out, int out_size) {
    const float* sen_emb  = (const float*)d_in[0];
    const float* hiddens  = (const float*)d_in[1];
    const int*   pos_raw  = (const int*)  d_in[2];
    const float* dim_up   = (const float*)d_in[3];
    const float* dim_down = (const float*)d_in[4];
    const float* dim_out  = (const float*)d_in[5];
    const float* W_gcn    = (const float*)d_in[6];
    const float* Wi       = (const float*)d_in[8];
    const float* Wh       = (const float*)d_in[9];
    const float* bi       = (const float*)d_in[10];
    const float* bh       = (const float*)d_in[11];
    const float* cur_h    = (const float*)d_in[12];
    const float* cur_cell = (const float*)d_in[13];
    float* out = (float*)d_out;

    float *p_vecA, *p_vecB, *p_inp;
    cudaGetSymbolAddress((void**)&p_vecA, g_vecA);
    cudaGetSymbolAddress((void**)&p_vecB, g_vecB);
    cudaGetSymbolAddress((void**)&p_inp,  g_inp);

    // inp[0:D) = sen_emb, inp[2D] = pos (graph slot filled later)
    k_prep_inp<<<D / 256, 256>>>(sen_emb, pos_raw);

    // s = colsum(hiddens)
    k_colsum_partial<<<dim3(D / 256, 32), 256>>>(hiddens);
    k_colsum_reduce<<<D / 256, 256>>>();

    // m = (s @ dim_up + cur_h) / (S+1)
    k_lmv_partial<<<dim3(D / 256, 16), 256>>>(p_vecA, dim_up);
    k_lmv_reduce<<<D / 256, 256>>>(p_vecB, cur_h, 1.0f / (float)N_NODES, 0);

    // v2 = relu(m @ W_gcn)
    k_lmv_partial<<<dim3(D / 256, 16), 256>>>(p_vecB, W_gcn);
    k_lmv_reduce<<<D / 256, 256>>>(p_vecA, nullptr, 1.0f, 1);

    // graph_emb = v2 @ dim_down  -> inp[D : 2D)
    k_lmv_partial<<<dim3(D / 256, 16), 256>>>(p_vecA, dim_down);
    k_lmv_reduce<<<D / 256, 256>>>(p_inp + D, nullptr, 1.0f, 0);

    // LSTM gate pre-activations (8192 warps, one per (gate,row))
    k_gsum<<<(4 * D) / 8, 256>>>(Wi, Wh, bi, bh, cur_h);
    k_gates<<<D / 256, 256>>>(cur_cell);

    // out = new_h @ dim_out
    k_out_partial<<<dim3(NT / 256, 16), 256>>>(dim_out);
    k_out_reduce<<<NT / 256, 256>>>(out);
}

// round 2
// speedup vs baseline: 1.0028x; 1.0028x over previous
#include <cuda_runtime.h>
#include <cstdint>
#include <cstddef>

// Problem constants
#define S_LEN 4096
#define D 2048
#define DV 512            // D / 4 (float4 columns)
#define NT 32000
#define NTV 8000          // NT / 4
#define INP 4097          // D + D + 1
#define N_NODES 4097      // S_LEN + 1

// ---------------- scratch (device globals; no allocation) ----------------
__device__ float g_part_cs[64 * D];     // column-sum partials
__device__ float g_vecA[D];             // s (colsum), then v2
__device__ float g_vecB[D];             // m (mean msg)
__device__ float g_part[64 * D];        // left-matvec partials
__device__ float g_inp[INP];            // LSTM input vector
__device__ float g_gsum[4 * D];         // gate pre-activations
__device__ float g_newh[D];             // new hidden
__device__ float g_pout[16 * NT];       // output matvec partials (2 MB)

// ---------------- kernels ----------------

// Column sum of hiddens [S_LEN, D] -> partials [64][D], float4 path.
// grid (2, 64), block 256. Each chunk = 64 rows.
__global__ void k_colsum_partial(const float4* __restrict__ hid4) {
    int c  = blockIdx.x * 256 + threadIdx.x;   // vec col [0, 512)
    int r0 = blockIdx.y * 64;
    float4 a = make_float4(0.f, 0.f, 0.f, 0.f);
    #pragma unroll 8
    for (int r = 0; r < 64; ++r) {
        float4 v = hid4[(size_t)(r0 + r) * DV + c];
        a.x += v.x; a.y += v.y; a.z += v.z; a.w += v.w;
    }
    ((float4*)g_part_cs)[blockIdx.y * DV + c] = a;
}

// grid (2), block 256
__global__ void k_colsum_reduce() {
    int c = blockIdx.x * 256 + threadIdx.x;
    float4 a = make_float4(0.f, 0.f, 0.f, 0.f);
    #pragma unroll
    for (int k = 0; k < 64; ++k) {
        float4 v = ((const float4*)g_part_cs)[k * DV + c];
        a.x += v.x; a.y += v.y; a.z += v.z; a.w += v.w;
    }
    ((float4*)g_vecA)[c] = a;
}

// Left matvec partials: part[ks][col] = sum_{k in chunk} v[k] * W[k][col]
// grid (2, 64), block 256. Chunk = 32 rows, fully unrolled float4.
__global__ void k_lmv_partial(const float* __restrict__ v, const float4* __restrict__ W4) {
    int c  = blockIdx.x * 256 + threadIdx.x;   // vec col [0, 512)
    int k0 = blockIdx.y * 32;
    float4 a = make_float4(0.f, 0.f, 0.f, 0.f);
    #pragma unroll 8
    for (int k = 0; k < 32; ++k) {
        float s = __ldg(v + k0 + k);
        float4 w = W4[(size_t)(k0 + k) * DV + c];
        a.x += s * w.x; a.y += s * w.y; a.z += s * w.z; a.w += s * w.w;
    }
    ((float4*)g_part)[blockIdx.y * DV + c] = a;
}

// Reduce 64 partials with optional add-vector, scale, relu. grid (2), block 256.
__global__ void k_lmv_reduce(float* __restrict__ out, const float* __restrict__ addvec,
                             float scale, int do_relu) {
    int c = blockIdx.x * 256 + threadIdx.x;
    float4 a = make_float4(0.f, 0.f, 0.f, 0.f);
    #pragma unroll
    for (int k = 0; k < 64; ++k) {
        float4 v = ((const float4*)g_part)[k * DV + c];
        a.x += v.x; a.y += v.y; a.z += v.z; a.w += v.w;
    }
    if (addvec) {
        const float4 b = ((const float4*)addvec)[c];
        a.x += b.x; a.y += b.y; a.z += b.z; a.w += b.w;
    }
    a.x *= scale; a.y *= scale; a.z *= scale; a.w *= scale;
    if (do_relu) {
        a.x = fmaxf(a.x, 0.f); a.y = fmaxf(a.y, 0.f);
        a.z = fmaxf(a.z, 0.f); a.w = fmaxf(a.w, 0.f);
    }
    // out may be unaligned-by-4-elems target? No: all targets are D-aligned vectors.
    ((float4*)out)[c] = a;
}

// Fill g_inp[0:D) = sen_emb, g_inp[2D] = pos_index (dtype-defensive).
__global__ void k_prep_inp(const float* __restrict__ sen, const int* __restrict__ pos_raw) {
    int i = blockIdx.x * 256 + threadIdx.x;
    g_inp[i] = sen[i];
    if (i == 0) {
        int bits = pos_raw[0];
        float f;
        if (bits >= 0 && bits < 1000000) f = (float)bits;   // stored as integer
        else f = __int_as_float(bits);                      // stored as float32
        g_inp[2 * D] = f;
    }
}

// Gate pre-activations: one warp per (gate,row). 512 threads = 16 warps/block.
// grid = 8192/16 = 512 blocks. Scalar coalesced loads, unroll 16 for MLP.
__global__ void __launch_bounds__(512) k_gsum(
        const float* __restrict__ Wi, const float* __restrict__ Wh,
        const float* __restrict__ bi, const float* __restrict__ bh,
        const float* __restrict__ curh) {
    int warp = (blockIdx.x * 512 + threadIdx.x) >> 5;   // [0, 8192)
    int lane = threadIdx.x & 31;
    const float* wi_row = Wi + (size_t)warp * INP;
    const float* wh_row = Wh + (size_t)warp * D;
    float acc = 0.f;
    #pragma unroll 16
    for (int i = lane; i < INP; i += 32) acc += __ldg(wi_row + i) * g_inp[i];
    #pragma unroll 16
    for (int i = lane; i < D; i += 32) acc += __ldg(wh_row + i) * __ldg(curh + i);
    #pragma unroll
    for (int o = 16; o; o >>= 1) acc += __shfl_down_sync(0xffffffffu, acc, o);
    if (lane == 0) g_gsum[warp] = acc + bi[warp] + bh[warp];
}

__device__ __forceinline__ float sigf(float x) { return 1.f / (1.f + expf(-x)); }

__global__ void k_gates(const float* __restrict__ cur_cell) {
    int h = blockIdx.x * 256 + threadIdx.x;
    float i_g = sigf(g_gsum[h]);
    float f_g = sigf(g_gsum[D + h]);
    float g_g = tanhf(g_gsum[2 * D + h]);
    float o_g = sigf(g_gsum[3 * D + h]);
    float nc  = f_g * cur_cell[h] + i_g * g_g;
    g_newh[h] = o_g * tanhf(nc);
}

// Output matvec partials: new_h (D) x dim_out [D, NT], float4 over columns.
// grid (32, 16), block 256. Chunk = 128 k-rows; new_h chunk staged in smem.
__global__ void __launch_bounds__(256) k_out_partial(const float4* __restrict__ W4) {
    __shared__ float sh[128];
    int k0 = blockIdx.y * 128;
    if (threadIdx.x < 128) sh[threadIdx.x] = g_newh[k0 + threadIdx.x];
    __syncthreads();
    int n4 = blockIdx.x * 256 + threadIdx.x;
    if (n4 >= NTV) return;
    float4 a = make_float4(0.f, 0.f, 0.f, 0.f);
    #pragma unroll 8
    for (int k = 0; k < 128; ++k) {
        float h = sh[k];
        float4 w = W4[(size_t)(k0 + k) * NTV + n4];
        a.x += h * w.x; a.y += h * w.y; a.z += h * w.z; a.w += h * w.w;
    }
    ((float4*)g_pout)[blockIdx.y * NTV + n4] = a;
}

// grid 32, block 256 (guarded).
__global__ void k_out_reduce(float* __restrict__ out) {
    int n4 = blockIdx.x * 256 + threadIdx.x;
    if (n4 >= NTV) return;
    float4 a = make_float4(0.f, 0.f, 0.f, 0.f);
    #pragma unroll
    for (int k = 0; k < 16; ++k) {
        float4 v = ((const float4*)g_pout)[k * NTV + n4];
        a.x += v.x; a.y += v.y; a.z += v.z; a.w += v.w;
    }
    ((float4*)out)[n4] = a;
}

// ---------------- launcher ----------------
// Inputs: 0 sen_emb [D], 1 hiddens [S,D], 2 pos_index [1], 3 dim_up [D,D],
// 4 dim_down [D,D], 5 dim_out [D,NT], 6 W_gcn [D,D], 7 att_w (unused; softmax
// over identical rows is exactly uniform), 8 Wi [4,D,INP], 9 Wh [4,D,D],
// 10 bi, 11 bh, 12 cur_h [D], 13 cur_cell [D]
extern "C" void kernel_launch(void* const* d_in, const int* in_sizes, int n_in,
                              void* d_out, int out_size) {
    const float* sen_emb  = (const float*)d_in[0];
    const float* hiddens  = (const float*)d_in[1];
    const int*   pos_raw  = (const int*)  d_in[2];
    const float* dim_up   = (const float*)d_in[3];
    const float* dim_down = (const float*)d_in[4];
    const float* dim_out  = (const float*)d_in[5];
    const float* W_gcn    = (const float*)d_in[6];
    const float* Wi       = (const float*)d_in[8];
    const float* Wh       = (const float*)d_in[9];
    const float* bi       = (const float*)d_in[10];
    const float* bh       = (const float*)d_in[11];
    const float* cur_h    = (const float*)d_in[12];
    const float* cur_cell = (const float*)d_in[13];
    float* out = (float*)d_out;

    float *p_vecA, *p_vecB, *p_inp;
    cudaGetSymbolAddress((void**)&p_vecA, g_vecA);
    cudaGetSymbolAddress((void**)&p_vecB, g_vecB);
    cudaGetSymbolAddress((void**)&p_inp,  g_inp);

    // inp[0:D) = sen_emb, inp[2D] = pos
    k_prep_inp<<<D / 256, 256>>>(sen_emb, pos_raw);

    // s = colsum(hiddens)
    k_colsum_partial<<<dim3(2, 64), 256>>>((const float4*)hiddens);
    k_colsum_reduce<<<2, 256>>>();

    // m = (s @ dim_up + cur_h) / (S+1)
    k_lmv_partial<<<dim3(2, 64), 256>>>(p_vecA, (const float4*)dim_up);
    k_lmv_reduce<<<2, 256>>>(p_vecB, cur_h, 1.0f / (float)N_NODES, 0);

    // v2 = relu(m @ W_gcn)
    k_lmv_partial<<<dim3(2, 64), 256>>>(p_vecB, (const float4*)W_gcn);
    k_lmv_reduce<<<2, 256>>>(p_vecA, nullptr, 1.0f, 1);

    // graph_emb = v2 @ dim_down  -> inp[D : 2D)
    k_lmv_partial<<<dim3(2, 64), 256>>>(p_vecA, (const float4*)dim_down);
    k_lmv_reduce<<<2, 256>>>(p_inp + D, nullptr, 1.0f, 0);

    // LSTM gate pre-activations (8192 warps, one per (gate,row))
    k_gsum<<<512, 512>>>(Wi, Wh, bi, bh, cur_h);
    k_gates<<<D / 256, 256>>>(cur_cell);

    // out = new_h @ dim_out
    k_out_partial<<<dim3(32, 16), 256>>>((const float4*)dim_out);
    k_out_reduce<<<32, 256>>>(out);
}

// round 4
// speedup vs baseline: 1.1403x; 1.1371x over previous
#include <cuda_runtime.h>
#include <cstdint>
#include <cstddef>

// Problem constants
#define S_LEN 4096
#define D 2048
#define DV 512            // D / 4 (float4 columns)
#define NT 32000
#define NTV 8000          // NT / 4
#define INP 4097          // D + D + 1
#define N_NODES 4097      // S_LEN + 1

// ---------------- scratch (device globals; no allocation) ----------------
__device__ float g_part_cs[128 * D];    // column-sum partials (1 MB)
__device__ float g_vecA[D];             // s (colsum), then v2
__device__ float g_vecB[D];             // m (mean msg)
__device__ float g_part[128 * D];       // left-matvec partials (1 MB)
__device__ float g_inp[INP];            // LSTM input vector
__device__ float g_gsum[4 * D];         // gate pre-activations
__device__ float g_newh[D];             // new hidden
__device__ float g_pout[16 * NT];       // output matvec partials (2 MB)

// ---------------- kernels ----------------

// Column sum of hiddens [S_LEN, D] -> partials [128][D].
// grid (2, 128), block 256. Chunk = 32 rows, two 16-deep explicit batches.
__global__ void __launch_bounds__(256) k_colsum_partial(const float4* __restrict__ hid4) {
    int c  = blockIdx.x * 256 + threadIdx.x;   // vec col [0, 512)
    int r0 = blockIdx.y * 32;
    float4 a = make_float4(0.f, 0.f, 0.f, 0.f);
    #pragma unroll
    for (int half = 0; half < 2; ++half) {
        float4 w[16];
        #pragma unroll
        for (int r = 0; r < 16; ++r)
            w[r] = hid4[(size_t)(r0 + half * 16 + r) * DV + c];
        #pragma unroll
        for (int r = 0; r < 16; ++r) {
            a.x += w[r].x; a.y += w[r].y; a.z += w[r].z; a.w += w[r].w;
        }
    }
    ((float4*)g_part_cs)[blockIdx.y * DV + c] = a;
}

// grid (8), block 256 — scalar columns for max parallelism.
__global__ void k_colsum_reduce() {
    int c = blockIdx.x * 256 + threadIdx.x;    // [0, 2048)
    float a = 0.f;
    #pragma unroll 16
    for (int k = 0; k < 128; ++k) a += g_part_cs[k * D + c];
    g_vecA[c] = a;
}

// Left matvec partials: part[chunk][col] = sum_{k in chunk} v[k] * W[k][col]
// grid (2, 128), block 256. Chunk = 16 rows, fully batched float4 loads.
__global__ void __launch_bounds__(256) k_lmv_partial(
        const float* __restrict__ v, const float4* __restrict__ W4) {
    int c  = blockIdx.x * 256 + threadIdx.x;   // vec col [0, 512)
    int k0 = blockIdx.y * 16;
    float4 w[16];
    #pragma unroll
    for (int k = 0; k < 16; ++k)
        w[k] = W4[(size_t)(k0 + k) * DV + c];
    float4 a = make_float4(0.f, 0.f, 0.f, 0.f);
    #pragma unroll
    for (int k = 0; k < 16; ++k) {
        float s = __ldg(v + k0 + k);
        a.x += s * w[k].x; a.y += s * w[k].y; a.z += s * w[k].z; a.w += s * w[k].w;
    }
    ((float4*)g_part)[blockIdx.y * DV + c] = a;
}

// Reduce 128 partials with optional add-vector, scale, relu. grid (8), block 256.
__global__ void k_lmv_reduce(float* __restrict__ out, const float* __restrict__ addvec,
                             float scale, int do_relu) {
    int c = blockIdx.x * 256 + threadIdx.x;    // [0, 2048)
    float a = 0.f;
    #pragma unroll 16
    for (int k = 0; k < 128; ++k) a += g_part[k * D + c];
    if (addvec) a += addvec[c];
    a *= scale;
    if (do_relu) a = fmaxf(a, 0.f);
    out[c] = a;
}

// Fill g_inp[0:D) = sen_emb, g_inp[2D] = pos_index (dtype-defensive).
__global__ void k_prep_inp(const float* __restrict__ sen, const int* __restrict__ pos_raw) {
    int i = blockIdx.x * 256 + threadIdx.x;
    g_inp[i] = sen[i];
    if (i == 0) {
        int bits = pos_raw[0];
        float f;
        if (bits >= 0 && bits < 1000000) f = (float)bits;   // stored as integer
        else f = __int_as_float(bits);                      // stored as float32
        g_inp[2 * D] = f;
    }
}

// Gate pre-activations: one warp per (gate,row). 512 threads = 16 warps/block.
// grid = 512 blocks. Wi rows: scalar (stride 4097, unaligned), explicit 16-batch.
// Wh rows: float4 (aligned), explicit 8-batch.
__global__ void __launch_bounds__(512) k_gsum(
        const float* __restrict__ Wi, const float4* __restrict__ Wh4,
        const float* __restrict__ bi, const float* __restrict__ bh,
        const float4* __restrict__ curh4) {
    int warp = (blockIdx.x * 512 + threadIdx.x) >> 5;   // [0, 8192)
    int lane = threadIdx.x & 31;
    const float* wi_row = Wi + (size_t)warp * INP;
    float acc = 0.f;
    // Wi dot inp: 4097 elems. 4096 in 8 batches of 16 (lane-strided), + tail.
    #pragma unroll
    for (int b = 0; b < 8; ++b) {
        float w[16];
        int base = b * 512 + lane;
        #pragma unroll
        for (int j = 0; j < 16; ++j) w[j] = __ldg(wi_row + base + j * 32);
        #pragma unroll
        for (int j = 0; j < 16; ++j) acc += w[j] * g_inp[base + j * 32];
    }
    if (lane == 0) acc += wi_row[4096] * g_inp[4096];
    // Wh dot cur_h: 512 float4 per row, 2 batches of 8.
    const float4* wh_row = Wh4 + (size_t)warp * DV;
    #pragma unroll
    for (int b = 0; b < 2; ++b) {
        float4 w[8];
        int base = b * 256 + lane;
        #pragma unroll
        for (int j = 0; j < 8; ++j) w[j] = __ldg(wh_row + base + j * 32);
        #pragma unroll
        for (int j = 0; j < 8; ++j) {
            float4 h = __ldg(curh4 + base + j * 32);
            acc += w[j].x * h.x + w[j].y * h.y + w[j].z * h.z + w[j].w * h.w;
        }
    }
    #pragma unroll
    for (int o = 16; o; o >>= 1) acc += __shfl_down_sync(0xffffffffu, acc, o);
    if (lane == 0) g_gsum[warp] = acc + bi[warp] + bh[warp];
}

__device__ __forceinline__ float sigf(float x) { return 1.f / (1.f + expf(-x)); }

__global__ void k_gates(const float* __restrict__ cur_cell) {
    int h = blockIdx.x * 256 + threadIdx.x;
    float i_g = sigf(g_gsum[h]);
    float f_g = sigf(g_gsum[D + h]);
    float g_g = tanhf(g_gsum[2 * D + h]);
    float o_g = sigf(g_gsum[3 * D + h]);
    float nc  = f_g * cur_cell[h] + i_g * g_g;
    g_newh[h] = o_g * tanhf(nc);
}

// Output matvec partials: new_h (D) x dim_out [D, NT], float4 over columns.
// grid (32, 16), block 256. Chunk = 128 k-rows, 8-deep explicit batches.
__global__ void __launch_bounds__(256) k_out_partial(const float4* __restrict__ W4) {
    __shared__ float sh[128];
    int k0 = blockIdx.y * 128;
    if (threadIdx.x < 128) sh[threadIdx.x] = g_newh[k0 + threadIdx.x];
    __syncthreads();
    int n4 = blockIdx.x * 256 + threadIdx.x;
    if (n4 >= NTV) return;
    float4 a = make_float4(0.f, 0.f, 0.f, 0.f);
    #pragma unroll 1
    for (int kb = 0; kb < 128; kb += 8) {
        float4 w[8];
        #pragma unroll
        for (int j = 0; j < 8; ++j)
            w[j] = W4[(size_t)(k0 + kb + j) * NTV + n4];
        #pragma unroll
        for (int j = 0; j < 8; ++j) {
            float h = sh[kb + j];
            a.x += h * w[j].x; a.y += h * w[j].y; a.z += h * w[j].z; a.w += h * w[j].w;
        }
    }
    ((float4*)g_pout)[blockIdx.y * NTV + n4] = a;
}

// grid 32, block 256 (guarded).
__global__ void k_out_reduce(float* __restrict__ out) {
    int n4 = blockIdx.x * 256 + threadIdx.x;
    if (n4 >= NTV) return;
    float4 a = make_float4(0.f, 0.f, 0.f, 0.f);
    #pragma unroll
    for (int k = 0; k < 16; ++k) {
        float4 v = ((const float4*)g_pout)[k * NTV + n4];
        a.x += v.x; a.y += v.y; a.z += v.z; a.w += v.w;
    }
    ((float4*)out)[n4] = a;
}

// ---------------- launcher ----------------
// Inputs: 0 sen_emb [D], 1 hiddens [S,D], 2 pos_index [1], 3 dim_up [D,D],
// 4 dim_down [D,D], 5 dim_out [D,NT], 6 W_gcn [D,D], 7 att_w (unused; softmax
// over identical rows is exactly uniform), 8 Wi [4,D,INP], 9 Wh [4,D,D],
// 10 bi, 11 bh, 12 cur_h [D], 13 cur_cell [D]
extern "C" void kernel_launch(void* const* d_in, const int* in_sizes, int n_in,
                              void* d_out, int out_size) {
    const float* sen_emb  = (const float*)d_in[0];
    const float* hiddens  = (const float*)d_in[1];
    const int*   pos_raw  = (const int*)  d_in[2];
    const float* dim_up   = (const float*)d_in[3];
    const float* dim_down = (const float*)d_in[4];
    const float* dim_out  = (const float*)d_in[5];
    const float* W_gcn    = (const float*)d_in[6];
    const float* Wi       = (const float*)d_in[8];
    const float* Wh       = (const float*)d_in[9];
    const float* bi       = (const float*)d_in[10];
    const float* bh       = (const float*)d_in[11];
    const float* cur_h    = (const float*)d_in[12];
    const float* cur_cell = (const float*)d_in[13];
    float* out = (float*)d_out;

    float *p_vecA, *p_vecB, *p_inp;
    cudaGetSymbolAddress((void**)&p_vecA, g_vecA);
    cudaGetSymbolAddress((void**)&p_vecB, g_vecB);
    cudaGetSymbolAddress((void**)&p_inp,  g_inp);

    // inp[0:D) = sen_emb, inp[2D] = pos
    k_prep_inp<<<D / 256, 256>>>(sen_emb, pos_raw);

    // s = colsum(hiddens)
    k_colsum_partial<<<dim3(2, 128), 256>>>((const float4*)hiddens);
    k_colsum_reduce<<<8, 256>>>();

    // m = (s @ dim_up + cur_h) / (S+1)
    k_lmv_partial<<<dim3(2, 128), 256>>>(p_vecA, (const float4*)dim_up);
    k_lmv_reduce<<<8, 256>>>(p_vecB, cur_h, 1.0f / (float)N_NODES, 0);

    // v2 = relu(m @ W_gcn)
    k_lmv_partial<<<dim3(2, 128), 256>>>(p_vecB, (const float4*)W_gcn);
    k_lmv_reduce<<<8, 256>>>(p_vecA, nullptr, 1.0f, 1);

    // graph_emb = v2 @ dim_down  -> inp[D : 2D)
    k_lmv_partial<<<dim3(2, 128), 256>>>(p_vecA, (const float4*)dim_down);
    k_lmv_reduce<<<8, 256>>>(p_inp + D, nullptr, 1.0f, 0);

    // LSTM gate pre-activations (8192 warps, one per (gate,row))
    k_gsum<<<512, 512>>>(Wi, (const float4*)Wh, bi, bh, (const float4*)cur_h);
    k_gates<<<D / 256, 256>>>(cur_cell);

    // out = new_h @ dim_out
    k_out_partial<<<dim3(32, 16), 256>>>((const float4*)dim_out);
    k_out_reduce<<<32, 256>>>(out);
}

// round 5
// speedup vs baseline: 1.2844x; 1.1264x over previous
#include <cuda_runtime.h>
#include <cstdint>
#include <cstddef>

// Problem constants
#define S_LEN 4096
#define D 2048
#define DV 512            // D / 4 (float4 columns)
#define NT 32000
#define NTV 8000          // NT / 4
#define INP 4097          // D + D + 1
#define N_NODES 4097      // S_LEN + 1
#define NP 256            // partial chunks for colsum / lmv stages

// ---------------- scratch (device globals; no allocation) ----------------
__device__ float g_bufA[NP * D];        // partial ping (2 MB)
__device__ float g_bufB[NP * D];        // partial pong (2 MB)
__device__ float g_inp[INP];            // LSTM input vector
__device__ float g_gsum[4 * D];         // gate pre-activations
__device__ float g_pout[16 * NT];       // output matvec partials (2 MB)

// ---------------- kernels ----------------

// Column sum of hiddens [S_LEN, D] -> partials bufA[256][D].
// grid (2, 256), block 256. Chunk = 16 rows, two 8-deep explicit batches.
__global__ void __launch_bounds__(256) k_colsum_partial(const float4* __restrict__ hid4) {
    int c  = blockIdx.x * 256 + threadIdx.x;   // vec col [0, 512)
    int r0 = blockIdx.y * 16;
    float4 a = make_float4(0.f, 0.f, 0.f, 0.f);
    #pragma unroll
    for (int half = 0; half < 2; ++half) {
        float4 w[8];
        #pragma unroll
        for (int r = 0; r < 8; ++r)
            w[r] = hid4[(size_t)(r0 + half * 8 + r) * DV + c];
        #pragma unroll
        for (int r = 0; r < 8; ++r) {
            a.x += w[r].x; a.y += w[r].y; a.z += w[r].z; a.w += w[r].w;
        }
    }
    ((float4*)g_bufA)[blockIdx.y * DV + c] = a;
}

// Fused matvec stage: prologue reduces the INPUT vector's 8 needed entries
// from partin (NP x D partial buffer), applies epilogue (addvec/scale/relu),
// then streams 8 rows of W accumulating partials into partout.
// grid (2, 256), block 256.
__global__ void __launch_bounds__(256) k_lmv_fused(
        const float* __restrict__ partin, const float4* __restrict__ W4,
        float* __restrict__ partout, const float* __restrict__ addvec,
        float scale, int do_relu) {
    __shared__ float red[256];
    __shared__ float vsh[8];
    int t  = threadIdx.x;
    int k0 = blockIdx.y * 8;
    // prologue: reduce partin over NP chunks for columns k0..k0+7
    {
        int c = k0 + (t & 7);
        int p0 = t >> 3;                       // 0..31
        float acc = 0.f;
        #pragma unroll
        for (int i = 0; i < 8; ++i)
            acc += partin[(p0 + i * 32) * D + c];
        red[t] = acc;
    }
    __syncthreads();
    #pragma unroll
    for (int s = 128; s >= 8; s >>= 1) {
        if (t < s) red[t] += red[t + s];
        __syncthreads();
    }
    if (t < 8) {
        float v = red[t];
        if (addvec) v += addvec[k0 + t];
        v *= scale;
        if (do_relu) v = fmaxf(v, 0.f);
        vsh[t] = v;
    }
    __syncthreads();
    // main: stream rows k0..k0+7 of W
    int c4 = blockIdx.x * 256 + t;
    float4 w[8];
    #pragma unroll
    for (int j = 0; j < 8; ++j)
        w[j] = W4[(size_t)(k0 + j) * DV + c4];
    float4 a = make_float4(0.f, 0.f, 0.f, 0.f);
    #pragma unroll
    for (int j = 0; j < 8; ++j) {
        float s_ = vsh[j];
        a.x += s_ * w[j].x; a.y += s_ * w[j].y; a.z += s_ * w[j].z; a.w += s_ * w[j].w;
    }
    ((float4*)partout)[blockIdx.y * DV + c4] = a;
}

// Final reduce of the dim_down partials -> g_inp[D : 2D). grid (8), block 256.
__global__ void k_fin_reduce(const float* __restrict__ partin) {
    int c = blockIdx.x * 256 + threadIdx.x;    // [0, 2048)
    float a = 0.f;
    #pragma unroll 16
    for (int k = 0; k < NP; ++k) a += partin[k * D + c];
    g_inp[D + c] = a;
}

// Fill g_inp[0:D) = sen_emb, g_inp[2D] = pos_index (dtype-defensive).
__global__ void k_prep_inp(const float* __restrict__ sen, const int* __restrict__ pos_raw) {
    int i = blockIdx.x * 256 + threadIdx.x;
    g_inp[i] = sen[i];
    if (i == 0) {
        int bits = pos_raw[0];
        float f;
        if (bits >= 0 && bits < 1000000) f = (float)bits;   // stored as integer
        else f = __int_as_float(bits);                      // stored as float32
        g_inp[2 * D] = f;
    }
}

// Gate pre-activations: one warp per (gate,row). 512 threads = 16 warps/block.
// grid = 512 blocks. Wi rows: scalar (stride 4097), explicit 16-batches.
// Wh rows: float4, explicit 8-batches.
__global__ void __launch_bounds__(512) k_gsum(
        const float* __restrict__ Wi, const float4* __restrict__ Wh4,
        const float* __restrict__ bi, const float* __restrict__ bh,
        const float4* __restrict__ curh4) {
    int warp = (blockIdx.x * 512 + threadIdx.x) >> 5;   // [0, 8192)
    int lane = threadIdx.x & 31;
    const float* wi_row = Wi + (size_t)warp * INP;
    float acc = 0.f;
    #pragma unroll
    for (int b = 0; b < 8; ++b) {
        float w[16];
        int base = b * 512 + lane;
        #pragma unroll
        for (int j = 0; j < 16; ++j) w[j] = __ldg(wi_row + base + j * 32);
        #pragma unroll
        for (int j = 0; j < 16; ++j) acc += w[j] * g_inp[base + j * 32];
    }
    if (lane == 0) acc += wi_row[4096] * g_inp[4096];
    const float4* wh_row = Wh4 + (size_t)warp * DV;
    #pragma unroll
    for (int b = 0; b < 2; ++b) {
        float4 w[8];
        int base = b * 256 + lane;
        #pragma unroll
        for (int j = 0; j < 8; ++j) w[j] = __ldg(wh_row + base + j * 32);
        #pragma unroll
        for (int j = 0; j < 8; ++j) {
            float4 h = __ldg(curh4 + base + j * 32);
            acc += w[j].x * h.x + w[j].y * h.y + w[j].z * h.z + w[j].w * h.w;
        }
    }
    #pragma unroll
    for (int o = 16; o; o >>= 1) acc += __shfl_down_sync(0xffffffffu, acc, o);
    if (lane == 0) g_gsum[warp] = acc + bi[warp] + bh[warp];
}

__device__ __forceinline__ float sigf(float x) { return 1.f / (1.f + expf(-x)); }

// Output matvec partials with the LSTM gate nonlinearity fused in.
// grid (32, 16), block 256. Chunk = 128 k-rows, 8-deep explicit batches.
__global__ void __launch_bounds__(256) k_out_partial(
        const float4* __restrict__ W4, const float* __restrict__ cur_cell) {
    __shared__ float sh[128];
    int k0 = blockIdx.y * 128;
    if (threadIdx.x < 128) {
        int k = k0 + threadIdx.x;
        float i_g = sigf(g_gsum[k]);
        float f_g = sigf(g_gsum[D + k]);
        float g_g = tanhf(g_gsum[2 * D + k]);
        float o_g = sigf(g_gsum[3 * D + k]);
        float nc  = f_g * cur_cell[k] + i_g * g_g;
        sh[threadIdx.x] = o_g * tanhf(nc);
    }
    __syncthreads();
    int n4 = blockIdx.x * 256 + threadIdx.x;
    if (n4 >= NTV) return;
    float4 a = make_float4(0.f, 0.f, 0.f, 0.f);
    #pragma unroll 1
    for (int kb = 0; kb < 128; kb += 8) {
        float4 w[8];
        #pragma unroll
        for (int j = 0; j < 8; ++j)
            w[j] = W4[(size_t)(k0 + kb + j) * NTV + n4];
        #pragma unroll
        for (int j = 0; j < 8; ++j) {
            float h = sh[kb + j];
            a.x += h * w[j].x; a.y += h * w[j].y; a.z += h * w[j].z; a.w += h * w[j].w;
        }
    }
    ((float4*)g_pout)[blockIdx.y * NTV + n4] = a;
}

// grid 32, block 256 (guarded).
__global__ void k_out_reduce(float* __restrict__ out) {
    int n4 = blockIdx.x * 256 + threadIdx.x;
    if (n4 >= NTV) return;
    float4 a = make_float4(0.f, 0.f, 0.f, 0.f);
    #pragma unroll
    for (int k = 0; k < 16; ++k) {
        float4 v = ((const float4*)g_pout)[k * NTV + n4];
        a.x += v.x; a.y += v.y; a.z += v.z; a.w += v.w;
    }
    ((float4*)out)[n4] = a;
}

// ---------------- launcher ----------------
// Inputs: 0 sen_emb [D], 1 hiddens [S,D], 2 pos_index [1], 3 dim_up [D,D],
// 4 dim_down [D,D], 5 dim_out [D,NT], 6 W_gcn [D,D], 7 att_w (unused; softmax
// over identical rows is exactly uniform), 8 Wi [4,D,INP], 9 Wh [4,D,D],
// 10 bi, 11 bh, 12 cur_h [D], 13 cur_cell [D]
extern "C" void kernel_launch(void* const* d_in, const int* in_sizes, int n_in,
                              void* d_out, int out_size) {
    const float* sen_emb  = (const float*)d_in[0];
    const float* hiddens  = (const float*)d_in[1];
    const int*   pos_raw  = (const int*)  d_in[2];
    const float* dim_up   = (const float*)d_in[3];
    const float* dim_down = (const float*)d_in[4];
    const float* dim_out  = (const float*)d_in[5];
    const float* W_gcn    = (const float*)d_in[6];
    const float* Wi       = (const float*)d_in[8];
    const float* Wh       = (const float*)d_in[9];
    const float* bi       = (const float*)d_in[10];
    const float* bh       = (const float*)d_in[11];
    const float* cur_h    = (const float*)d_in[12];
    const float* cur_cell = (const float*)d_in[13];
    float* out = (float*)d_out;

    float *pA, *pB;
    cudaGetSymbolAddress((void**)&pA, g_bufA);
    cudaGetSymbolAddress((void**)&pB, g_bufB);

    // inp[0:D) = sen_emb, inp[2D] = pos
    k_prep_inp<<<D / 256, 256>>>(sen_emb, pos_raw);

    // colsum partials -> bufA
    k_colsum_partial<<<dim3(2, 256), 256>>>((const float4*)hiddens);

    // stage up:   v = reduce(bufA);               partials(v @ dim_up)   -> bufB
    k_lmv_fused<<<dim3(2, 256), 256>>>(pA, (const float4*)dim_up,  pB,
                                       nullptr, 1.0f, 0);
    // stage gcn:  v = (reduce(bufB)+cur_h)/4097;  partials(v @ W_gcn)    -> bufA
    k_lmv_fused<<<dim3(2, 256), 256>>>(pB, (const float4*)W_gcn,   pA,
                                       cur_h, 1.0f / (float)N_NODES, 0);
    // stage down: v = relu(reduce(bufA));         partials(v @ dim_down) -> bufB
    k_lmv_fused<<<dim3(2, 256), 256>>>(pA, (const float4*)dim_down, pB,
                                       nullptr, 1.0f, 1);
    // graph_emb -> g_inp[D : 2D)
    k_fin_reduce<<<8, 256>>>(pB);

    // LSTM gate pre-activations (8192 warps, one per (gate,row))
    k_gsum<<<512, 512>>>(Wi, (const float4*)Wh, bi, bh, (const float4*)cur_h);

    // out = new_h @ dim_out (gates fused into partial kernel)
    k_out_partial<<<dim3(32, 16), 256>>>((const float4*)dim_out, cur_cell);
    k_out_reduce<<<32, 256>>>(out);
}

// round 6
// speedup vs baseline: 1.3051x; 1.0161x over previous
#include <cuda_runtime.h>
#include <cstdint>
#include <cstddef>

// Problem constants
#define S_LEN 4096
#define D 2048
#define DV 512            // D / 4 (float4 columns)
#define NT 32000
#define NTV 8000          // NT / 4
#define INP 4097          // D + D + 1
#define N_NODES 4097      // S_LEN + 1
#define NP 256            // partial chunks for colsum / lmv stages

// ---------------- scratch (device globals; no allocation) ----------------
__device__ float g_bufA[NP * D];        // partial ping (2 MB)
__device__ float g_bufB[NP * D];        // partial pong (2 MB)
__device__ float g_inp[INP];            // LSTM input vector
__device__ float g_gsum[4 * D];         // gate pre-activations
__device__ float g_pout[16 * NT];       // output matvec partials (2 MB)

// ---------------- kernels ----------------

// Column sum of hiddens [S_LEN, D] -> partials bufA[256][D].
// grid (2, 256), block 256. Chunk = 16 rows, one 16-deep explicit batch.
__global__ void __launch_bounds__(256) k_colsum_partial(const float4* __restrict__ hid4) {
    int c  = blockIdx.x * 256 + threadIdx.x;   // vec col [0, 512)
    int r0 = blockIdx.y * 16;
    float4 w[16];
    #pragma unroll
    for (int r = 0; r < 16; ++r)
        w[r] = hid4[(size_t)(r0 + r) * DV + c];
    float4 a = make_float4(0.f, 0.f, 0.f, 0.f);
    #pragma unroll
    for (int r = 0; r < 16; ++r) {
        a.x += w[r].x; a.y += w[r].y; a.z += w[r].z; a.w += w[r].w;
    }
    ((float4*)g_bufA)[blockIdx.y * DV + c] = a;
}

// Fused matvec stage. W rows are prefetched FIRST so their DRAM latency
// overlaps the prologue partial-reduction (L2 traffic + barriers).
// grid (2, 256), block 256.
__global__ void __launch_bounds__(256) k_lmv_fused(
        const float* __restrict__ partin, const float4* __restrict__ W4,
        float* __restrict__ partout, const float* __restrict__ addvec,
        float scale, int do_relu) {
    __shared__ float red[256];
    __shared__ float vsh[8];
    int t  = threadIdx.x;
    int k0 = blockIdx.y * 8;

    // 1) prefetch the 8 W rows this block streams (independent of prologue)
    int c4 = blockIdx.x * 256 + t;
    float4 w[8];
    #pragma unroll
    for (int j = 0; j < 8; ++j)
        w[j] = W4[(size_t)(k0 + j) * DV + c4];

    // 2) prologue: reduce partin over NP chunks for columns k0..k0+7
    {
        int c  = k0 + (t & 7);
        int p0 = t >> 3;                       // 0..31
        float acc = 0.f;
        #pragma unroll
        for (int i = 0; i < 8; ++i)
            acc += partin[(p0 + i * 32) * D + c];
        red[t] = acc;
    }
    __syncthreads();
    #pragma unroll
    for (int s = 128; s >= 8; s >>= 1) {
        if (t < s) red[t] += red[t + s];
        __syncthreads();
    }
    if (t < 8) {
        float v = red[t];
        if (addvec) v += addvec[k0 + t];
        v *= scale;
        if (do_relu) v = fmaxf(v, 0.f);
        vsh[t] = v;
    }
    __syncthreads();

    // 3) FMA with the prefetched W rows
    float4 a = make_float4(0.f, 0.f, 0.f, 0.f);
    #pragma unroll
    for (int j = 0; j < 8; ++j) {
        float s_ = vsh[j];
        a.x += s_ * w[j].x; a.y += s_ * w[j].y; a.z += s_ * w[j].z; a.w += s_ * w[j].w;
    }
    ((float4*)partout)[blockIdx.y * DV + c4] = a;
}

// Final reduce of the dim_down partials -> g_inp[D : 2D). grid (8), block 256.
__global__ void k_fin_reduce(const float* __restrict__ partin) {
    int c = blockIdx.x * 256 + threadIdx.x;    // [0, 2048)
    float a = 0.f;
    #pragma unroll 16
    for (int k = 0; k < NP; ++k) a += partin[k * D + c];
    g_inp[D + c] = a;
}

// Fill g_inp[0:D) = sen_emb, g_inp[2D] = pos_index (dtype-defensive).
__global__ void k_prep_inp(const float* __restrict__ sen, const int* __restrict__ pos_raw) {
    int i = blockIdx.x * 256 + threadIdx.x;
    g_inp[i] = sen[i];
    if (i == 0) {
        int bits = pos_raw[0];
        float f;
        if (bits >= 0 && bits < 1000000) f = (float)bits;   // stored as integer
        else f = __int_as_float(bits);                      // stored as float32
        g_inp[2 * D] = f;
    }
}

// Gate pre-activations: one warp per (gate,row). 512 threads = 16 warps/block.
// grid = 512 blocks. Wi rows: scalar (stride 4097), explicit 16-batches.
// Wh rows: float4, explicit 8-batches.
__global__ void __launch_bounds__(512) k_gsum(
        const float* __restrict__ Wi, const float4* __restrict__ Wh4,
        const float* __restrict__ bi, const float* __restrict__ bh,
        const float4* __restrict__ curh4) {
    int warp = (blockIdx.x * 512 + threadIdx.x) >> 5;   // [0, 8192)
    int lane = threadIdx.x & 31;
    const float* wi_row = Wi + (size_t)warp * INP;
    float acc = 0.f;
    #pragma unroll
    for (int b = 0; b < 8; ++b) {
        float w[16];
        int base = b * 512 + lane;
        #pragma unroll
        for (int j = 0; j < 16; ++j) w[j] = __ldg(wi_row + base + j * 32);
        #pragma unroll
        for (int j = 0; j < 16; ++j) acc += w[j] * g_inp[base + j * 32];
    }
    if (lane == 0) acc += wi_row[4096] * g_inp[4096];
    const float4* wh_row = Wh4 + (size_t)warp * DV;
    #pragma unroll
    for (int b = 0; b < 2; ++b) {
        float4 w[8];
        int base = b * 256 + lane;
        #pragma unroll
        for (int j = 0; j < 8; ++j) w[j] = __ldg(wh_row + base + j * 32);
        #pragma unroll
        for (int j = 0; j < 8; ++j) {
            float4 h = __ldg(curh4 + base + j * 32);
            acc += w[j].x * h.x + w[j].y * h.y + w[j].z * h.z + w[j].w * h.w;
        }
    }
    #pragma unroll
    for (int o = 16; o; o >>= 1) acc += __shfl_down_sync(0xffffffffu, acc, o);
    if (lane == 0) g_gsum[warp] = acc + bi[warp] + bh[warp];
}

__device__ __forceinline__ float sigf(float x) { return 1.f / (1.f + expf(-x)); }

// Output matvec partials with the LSTM gate nonlinearity fused in.
// grid (32, 16), block 256. Chunk = 128 k-rows, 16-deep explicit batches.
__global__ void __launch_bounds__(256) k_out_partial(
        const float4* __restrict__ W4, const float* __restrict__ cur_cell) {
    __shared__ float sh[128];
    int k0 = blockIdx.y * 128;
    if (threadIdx.x < 128) {
        int k = k0 + threadIdx.x;
        float i_g = sigf(g_gsum[k]);
        float f_g = sigf(g_gsum[D + k]);
        float g_g = tanhf(g_gsum[2 * D + k]);
        float o_g = sigf(g_gsum[3 * D + k]);
        float nc  = f_g * cur_cell[k] + i_g * g_g;
        sh[threadIdx.x] = o_g * tanhf(nc);
    }
    __syncthreads();
    int n4 = blockIdx.x * 256 + threadIdx.x;
    if (n4 >= NTV) return;
    float4 a = make_float4(0.f, 0.f, 0.f, 0.f);
    #pragma unroll 1
    for (int kb = 0; kb < 128; kb += 16) {
        float4 w[16];
        #pragma unroll
        for (int j = 0; j < 16; ++j)
            w[j] = W4[(size_t)(k0 + kb + j) * NTV + n4];
        #pragma unroll
        for (int j = 0; j < 16; ++j) {
            float h = sh[kb + j];
            a.x += h * w[j].x; a.y += h * w[j].y; a.z += h * w[j].z; a.w += h * w[j].w;
        }
    }
    ((float4*)g_pout)[blockIdx.y * NTV + n4] = a;
}

// grid 32, block 256 (guarded).
__global__ void k_out_reduce(float* __restrict__ out) {
    int n4 = blockIdx.x * 256 + threadIdx.x;
    if (n4 >= NTV) return;
    float4 a = make_float4(0.f, 0.f, 0.f, 0.f);
    #pragma unroll
    for (int k = 0; k < 16; ++k) {
        float4 v = ((const float4*)g_pout)[k * NTV + n4];
        a.x += v.x; a.y += v.y; a.z += v.z; a.w += v.w;
    }
    ((float4*)out)[n4] = a;
}

// ---------------- launcher ----------------
// Inputs: 0 sen_emb [D], 1 hiddens [S,D], 2 pos_index [1], 3 dim_up [D,D],
// 4 dim_down [D,D], 5 dim_out [D,NT], 6 W_gcn [D,D], 7 att_w (unused; softmax
// over identical rows is exactly uniform), 8 Wi [4,D,INP], 9 Wh [4,D,D],
// 10 bi, 11 bh, 12 cur_h [D], 13 cur_cell [D]
extern "C" void kernel_launch(void* const* d_in, const int* in_sizes, int n_in,
                              void* d_out, int out_size) {
    const float* sen_emb  = (const float*)d_in[0];
    const float* hiddens  = (const float*)d_in[1];
    const int*   pos_raw  = (const int*)  d_in[2];
    const float* dim_up   = (const float*)d_in[3];
    const float* dim_down = (const float*)d_in[4];
    const float* dim_out  = (const float*)d_in[5];
    const float* W_gcn    = (const float*)d_in[6];
    const float* Wi       = (const float*)d_in[8];
    const float* Wh       = (const float*)d_in[9];
    const float* bi       = (const float*)d_in[10];
    const float* bh       = (const float*)d_in[11];
    const float* cur_h    = (const float*)d_in[12];
    const float* cur_cell = (const float*)d_in[13];
    float* out = (float*)d_out;

    float *pA, *pB;
    cudaGetSymbolAddress((void**)&pA, g_bufA);
    cudaGetSymbolAddress((void**)&pB, g_bufB);

    // inp[0:D) = sen_emb, inp[2D] = pos
    k_prep_inp<<<D / 256, 256>>>(sen_emb, pos_raw);

    // colsum partials -> bufA
    k_colsum_partial<<<dim3(2, 256), 256>>>((const float4*)hiddens);

    // stage up:   v = reduce(bufA);               partials(v @ dim_up)   -> bufB
    k_lmv_fused<<<dim3(2, 256), 256>>>(pA, (const float4*)dim_up,  pB,
                                       nullptr, 1.0f, 0);
    // stage gcn:  v = (reduce(bufB)+cur_h)/4097;  partials(v @ W_gcn)    -> bufA
    k_lmv_fused<<<dim3(2, 256), 256>>>(pB, (const float4*)W_gcn,   pA,
                                       cur_h, 1.0f / (float)N_NODES, 0);
    // stage down: v = relu(reduce(bufA));         partials(v @ dim_down) -> bufB
    k_lmv_fused<<<dim3(2, 256), 256>>>(pA, (const float4*)dim_down, pB,
                                       nullptr, 1.0f, 1);
    // graph_emb -> g_inp[D : 2D)
    k_fin_reduce<<<8, 256>>>(pB);

    // LSTM gate pre-activations (8192 warps, one per (gate,row))
    k_gsum<<<512, 512>>>(Wi, (const float4*)Wh, bi, bh, (const float4*)cur_h);

    // out = new_h @ dim_out (gates fused into partial kernel)
    k_out_partial<<<dim3(32, 16), 256>>>((const float4*)dim_out, cur_cell);
    k_out_reduce<<<32, 256>>>(out);
}

// round 7
// speedup vs baseline: 1.3832x; 1.0598x over previous
#include <cuda_runtime.h>
#include <cstdint>
#include <cstddef>

// Problem constants
#define S_LEN 4096
#define D 2048
#define DV 512            // D / 4 (float4 columns)
#define NT 32000
#define NTV 8000          // NT / 4
#define INP 4097          // D + D + 1
#define N_NODES 4097      // S_LEN + 1
#define NP 256            // partial chunks for colsum / lmv stages
#define NBLK 296          // 2 blocks/SM on 148 SMs (co-resident by launch_bounds)
#define NTHR (NBLK * 256)
#define NWARP (NTHR / 32)

// ---------------- scratch (device globals; no allocation) ----------------
__device__ float g_bufA[NP * D];        // partial ping (2 MB)
__device__ float g_bufB[NP * D];        // partial pong (2 MB)
__device__ float g_inp[INP];            // LSTM input vector
__device__ float g_gsum[4 * D];         // gate pre-activations
__device__ float g_pout[16 * NT];       // output matvec partials (2 MB)
__device__ unsigned g_bar_cnt;          // zero-init; always returns to 0
__device__ volatile unsigned g_bar_gen; // monotonically increasing generation

// ---------------- grid-wide barrier (all NBLK blocks co-resident) --------
__device__ __forceinline__ void grid_bar() {
    __syncthreads();
    if (threadIdx.x == 0) {
        unsigned gen = g_bar_gen;
        __threadfence();                       // publish this block's phase writes
        if (atomicAdd(&g_bar_cnt, 1u) == NBLK - 1u) {
            g_bar_cnt = 0u;
            __threadfence();                   // reset visible before release
            g_bar_gen = gen + 1u;
        } else {
            while (g_bar_gen == gen) { }
        }
    }
    __syncthreads();
}

__device__ __forceinline__ float sigf(float x) { return 1.f / (1.f + expf(-x)); }

// Fused matvec stage over 512 virtual tiles (256 k-chunks x 2 column halves).
// Prologue reduces the 8 needed input entries from the NP x D partial buffer
// (W rows prefetched first so DRAM latency overlaps the reduce+barriers).
__device__ void lmv_stage(const float* __restrict__ partin,
                          const float4* __restrict__ W4,
                          float* __restrict__ partout,
                          const float* __restrict__ addvec,
                          float scale, int do_relu,
                          float* red, float* vsh) {
    int t = threadIdx.x;
    for (int vt = blockIdx.x; vt < 512; vt += NBLK) {
        int ky = vt >> 1;
        int k0 = ky * 8;
        int c4 = (vt & 1) * 256 + t;
        // prefetch W rows (independent of prologue)
        float4 w[8];
        #pragma unroll
        for (int j = 0; j < 8; ++j)
            w[j] = W4[(size_t)(k0 + j) * DV + c4];
        // prologue: reduce partin over NP chunks for columns k0..k0+7
        {
            int c  = k0 + (t & 7);
            int p0 = t >> 3;                   // 0..31
            float acc = 0.f;
            #pragma unroll
            for (int i = 0; i < 8; ++i)
                acc += partin[(p0 + i * 32) * D + c];
            __syncthreads();                   // guard red reuse across tiles
            red[t] = acc;
        }
        __syncthreads();
        #pragma unroll
        for (int s = 128; s >= 8; s >>= 1) {
            if (t < s) red[t] += red[t + s];
            __syncthreads();
        }
        if (t < 8) {
            float v = red[t];
            if (addvec) v += addvec[k0 + t];
            v *= scale;
            if (do_relu) v = fmaxf(v, 0.f);
            vsh[t] = v;
        }
        __syncthreads();
        float4 a = make_float4(0.f, 0.f, 0.f, 0.f);
        #pragma unroll
        for (int j = 0; j < 8; ++j) {
            float s_ = vsh[j];
            a.x += s_ * w[j].x; a.y += s_ * w[j].y;
            a.z += s_ * w[j].z; a.w += s_ * w[j].w;
        }
        ((float4*)partout)[ky * DV + c4] = a;
    }
}

// ---------------- the whole network in one persistent kernel -------------
__global__ void __launch_bounds__(256, 2) k_mega(
        const float* __restrict__ sen, const int* __restrict__ pos_raw,
        const float4* __restrict__ hid4,
        const float4* __restrict__ dim_up4, const float4* __restrict__ W_gcn4,
        const float4* __restrict__ dim_down4, const float4* __restrict__ dim_out4,
        const float* __restrict__ Wi, const float4* __restrict__ Wh4,
        const float* __restrict__ bi, const float* __restrict__ bh,
        const float* __restrict__ cur_h, const float* __restrict__ cur_cell,
        float* __restrict__ out) {
    __shared__ float red[256];
    __shared__ float vsh[128];
    int t = threadIdx.x;
    int g = blockIdx.x * 256 + t;
    int wg = g >> 5, lane = t & 31;

    // ---- P0: prep g_inp + column-sum partials of hiddens -> bufA ----
    if (g < D) g_inp[g] = sen[g];
    if (g == D) {
        int bits = pos_raw[0];
        g_inp[2 * D] = (bits >= 0 && bits < 1000000) ? (float)bits
                                                     : __int_as_float(bits);
    }
    for (int item = g; item < NP * DV; item += NTHR) {
        int chunk = item >> 9, c4 = item & 511;
        float4 w[16];
        #pragma unroll
        for (int r = 0; r < 16; ++r)
            w[r] = hid4[(size_t)(chunk * 16 + r) * DV + c4];
        float4 a = make_float4(0.f, 0.f, 0.f, 0.f);
        #pragma unroll
        for (int r = 0; r < 16; ++r) {
            a.x += w[r].x; a.y += w[r].y; a.z += w[r].z; a.w += w[r].w;
        }
        ((float4*)g_bufA)[item] = a;           // item == chunk*DV + c4
    }
    grid_bar();

    // ---- P1..P3: graph chain ----
    lmv_stage(g_bufA, dim_up4,   g_bufB, nullptr, 1.0f, 0, red, vsh);
    grid_bar();
    lmv_stage(g_bufB, W_gcn4,    g_bufA, cur_h, 1.0f / (float)N_NODES, 0, red, vsh);
    grid_bar();
    lmv_stage(g_bufA, dim_down4, g_bufB, nullptr, 1.0f, 1, red, vsh);
    grid_bar();

    // ---- P4: final reduce of dim_down partials -> g_inp[D : 2D) ----
    for (int c = wg; c < D; c += NWARP) {
        float a = 0.f;
        #pragma unroll
        for (int i = 0; i < 8; ++i)
            a += g_bufB[(lane + i * 32) * D + c];
        #pragma unroll
        for (int o = 16; o; o >>= 1) a += __shfl_down_sync(0xffffffffu, a, o);
        if (lane == 0) g_inp[D + c] = a;
    }
    grid_bar();

    // ---- P5: LSTM gate pre-activations, warp per (gate,row) ----
    for (int row = wg; row < 4 * D; row += NWARP) {
        const float* wi_row = Wi + (size_t)row * INP;
        float acc = 0.f;
        #pragma unroll
        for (int b = 0; b < 8; ++b) {
            float w[16];
            int base = b * 512 + lane;
            #pragma unroll
            for (int j = 0; j < 16; ++j) w[j] = __ldg(wi_row + base + j * 32);
            #pragma unroll
            for (int j = 0; j < 16; ++j) acc += w[j] * g_inp[base + j * 32];
        }
        if (lane == 0) acc += wi_row[4096] * g_inp[4096];
        const float4* wh_row = Wh4 + (size_t)row * DV;
        const float4* curh4  = (const float4*)cur_h;
        #pragma unroll
        for (int b = 0; b < 2; ++b) {
            float4 w[8];
            int base = b * 256 + lane;
            #pragma unroll
            for (int j = 0; j < 8; ++j) w[j] = __ldg(wh_row + base + j * 32);
            #pragma unroll
            for (int j = 0; j < 8; ++j) {
                float4 h = __ldg(curh4 + base + j * 32);
                acc += w[j].x * h.x + w[j].y * h.y + w[j].z * h.z + w[j].w * h.w;
            }
        }
        #pragma unroll
        for (int o = 16; o; o >>= 1) acc += __shfl_down_sync(0xffffffffu, acc, o);
        if (lane == 0) g_gsum[row] = acc + bi[row] + bh[row];
    }
    grid_bar();

    // ---- P6: output matvec partials with fused LSTM gates ----
    for (int vt = blockIdx.x; vt < 512; vt += NBLK) {
        int kc = vt >> 5, nb = vt & 31;
        int k0 = kc * 128;
        __syncthreads();                       // guard vsh reuse across tiles
        if (t < 128) {
            int k = k0 + t;
            float i_g = sigf(g_gsum[k]);
            float f_g = sigf(g_gsum[D + k]);
            float g_g = tanhf(g_gsum[2 * D + k]);
            float o_g = sigf(g_gsum[3 * D + k]);
            float nc  = f_g * cur_cell[k] + i_g * g_g;
            vsh[t] = o_g * tanhf(nc);
        }
        __syncthreads();
        int n4 = nb * 256 + t;
        if (n4 < NTV) {
            float4 a = make_float4(0.f, 0.f, 0.f, 0.f);
            #pragma unroll 1
            for (int kb = 0; kb < 128; kb += 16) {
                float4 w[16];
                #pragma unroll
                for (int j = 0; j < 16; ++j)
                    w[j] = dim_out4[(size_t)(k0 + kb + j) * NTV + n4];
                #pragma unroll
                for (int j = 0; j < 16; ++j) {
                    float h = vsh[kb + j];
                    a.x += h * w[j].x; a.y += h * w[j].y;
                    a.z += h * w[j].z; a.w += h * w[j].w;
                }
            }
            ((float4*)g_pout)[kc * NTV + n4] = a;
        }
    }
    grid_bar();

    // ---- P7: output reduce ----
    for (int n4 = g; n4 < NTV; n4 += NTHR) {
        float4 a = make_float4(0.f, 0.f, 0.f, 0.f);
        #pragma unroll
        for (int k = 0; k < 16; ++k) {
            float4 v = ((const float4*)g_pout)[k * NTV + n4];
            a.x += v.x; a.y += v.y; a.z += v.z; a.w += v.w;
        }
        ((float4*)out)[n4] = a;
    }
}

// ---------------- launcher ----------------
// Inputs: 0 sen_emb [D], 1 hiddens [S,D], 2 pos_index [1], 3 dim_up [D,D],
// 4 dim_down [D,D], 5 dim_out [D,NT], 6 W_gcn [D,D], 7 att_w (unused; softmax
// over identical rows is exactly uniform), 8 Wi [4,D,INP], 9 Wh [4,D,D],
// 10 bi, 11 bh, 12 cur_h [D], 13 cur_cell [D]
extern "C" void kernel_launch(void* const* d_in, const int* in_sizes, int n_in,
                              void* d_out, int out_size) {
    const float* sen_emb  = (const float*)d_in[0];
    const float* hiddens  = (const float*)d_in[1];
    const int*   pos_raw  = (const int*)  d_in[2];
    const float* dim_up   = (const float*)d_in[3];
    const float* dim_down = (const float*)d_in[4];
    const float* dim_out  = (const float*)d_in[5];
    const float* W_gcn    = (const float*)d_in[6];
    const float* Wi       = (const float*)d_in[8];
    const float* Wh       = (const float*)d_in[9];
    const float* bi       = (const float*)d_in[10];
    const float* bh       = (const float*)d_in[11];
    const float* cur_h    = (const float*)d_in[12];
    const float* cur_cell = (const float*)d_in[13];
    float* out = (float*)d_out;

    k_mega<<<NBLK, 256>>>(
        sen_emb, pos_raw,
        (const float4*)hiddens,
        (const float4*)dim_up, (const float4*)W_gcn,
        (const float4*)dim_down, (const float4*)dim_out,
        Wi, (const float4*)Wh, bi, bh,
        cur_h, cur_cell, out);
}

// round 8
// speedup vs baseline: 1.4638x; 1.0582x over previous
#include <cuda_runtime.h>
#include <cstdint>
#include <cstddef>

// Problem constants
#define S_LEN 4096
#define D 2048
#define DV 512            // D / 4 (float4 columns)
#define NT 32000
#define NTV 8000          // NT / 4
#define INP 4097          // D + D + 1
#define N_NODES 4097      // S_LEN + 1
#define NP 256            // partial chunks for colsum / lmv stages
#define NBLK 296          // 2 blocks/SM on 148 SMs (co-resident by launch_bounds)
#define NTHR (NBLK * 256)
#define NWARP (NTHR / 32)

// ---------------- scratch (device globals; no allocation) ----------------
__device__ float g_bufA[NP * D];        // partial ping (2 MB)
__device__ float g_bufB[NP * D];        // partial pong (2 MB)
__device__ float g_inp[INP];            // LSTM input vector
__device__ float g_gsum[4 * D];         // gate pre-activations
__device__ float g_pout[16 * NT];       // output matvec partials (2 MB)
__device__ unsigned g_hbits[D / 32];    // per-warp ballots of cur_h != 0
__device__ unsigned g_hflag;            // OR of g_hbits (rewritten every launch)
__device__ unsigned g_bar_cnt;          // zero-init; always returns to 0
__device__ volatile unsigned g_bar_gen; // monotonically increasing generation

// ---------------- grid-wide barrier (all NBLK blocks co-resident) --------
__device__ __forceinline__ void grid_bar() {
    __syncthreads();
    if (threadIdx.x == 0) {
        unsigned gen = g_bar_gen;
        __threadfence();                       // publish this block's phase writes
        if (atomicAdd(&g_bar_cnt, 1u) == NBLK - 1u) {
            g_bar_cnt = 0u;
            __threadfence();                   // reset visible before release
            g_bar_gen = gen + 1u;
        } else {
            while (g_bar_gen == gen) { }
        }
    }
    __syncthreads();
}

__device__ __forceinline__ float sigf(float x) { return 1.f / (1.f + expf(-x)); }

// Fused matvec stage over 512 virtual tiles (256 k-chunks x 2 column halves).
// Prologue reduces the 8 needed input entries from the NP x D partial buffer
// (W rows prefetched first so DRAM latency overlaps the reduce+barriers).
__device__ void lmv_stage(const float* __restrict__ partin,
                          const float4* __restrict__ W4,
                          float* __restrict__ partout,
                          const float* __restrict__ addvec,
                          float scale, int do_relu,
                          float* red, float* vsh) {
    int t = threadIdx.x;
    for (int vt = blockIdx.x; vt < 512; vt += NBLK) {
        int ky = vt >> 1;
        int k0 = ky * 8;
        int c4 = (vt & 1) * 256 + t;
        // prefetch W rows (independent of prologue)
        float4 w[8];
        #pragma unroll
        for (int j = 0; j < 8; ++j)
            w[j] = W4[(size_t)(k0 + j) * DV + c4];
        // prologue: reduce partin over NP chunks for columns k0..k0+7
        {
            int c  = k0 + (t & 7);
            int p0 = t >> 3;                   // 0..31
            float acc = 0.f;
            #pragma unroll
            for (int i = 0; i < 8; ++i)
                acc += partin[(p0 + i * 32) * D + c];
            __syncthreads();                   // guard red reuse across tiles
            red[t] = acc;
        }
        __syncthreads();
        #pragma unroll
        for (int s = 128; s >= 8; s >>= 1) {
            if (t < s) red[t] += red[t + s];
            __syncthreads();
        }
        if (t < 8) {
            float v = red[t];
            if (addvec) v += addvec[k0 + t];
            v *= scale;
            if (do_relu) v = fmaxf(v, 0.f);
            vsh[t] = v;
        }
        __syncthreads();
        float4 a = make_float4(0.f, 0.f, 0.f, 0.f);
        #pragma unroll
        for (int j = 0; j < 8; ++j) {
            float s_ = vsh[j];
            a.x += s_ * w[j].x; a.y += s_ * w[j].y;
            a.z += s_ * w[j].z; a.w += s_ * w[j].w;
        }
        ((float4*)partout)[ky * DV + c4] = a;
    }
}

// ---------------- the whole network in one persistent kernel -------------
__global__ void __launch_bounds__(256, 2) k_mega(
        const float* __restrict__ sen, const int* __restrict__ pos_raw,
        const float4* __restrict__ hid4,
        const float4* __restrict__ dim_up4, const float4* __restrict__ W_gcn4,
        const float4* __restrict__ dim_down4, const float4* __restrict__ dim_out4,
        const float* __restrict__ Wi, const float4* __restrict__ Wh4,
        const float* __restrict__ bi, const float* __restrict__ bh,
        const float* __restrict__ cur_h, const float* __restrict__ cur_cell,
        float* __restrict__ out) {
    __shared__ float red[256];
    __shared__ float vsh[128];
    int t = threadIdx.x;
    int g = blockIdx.x * 256 + t;
    int wg = g >> 5, lane = t & 31;

    // ---- P0: prep g_inp, ballot cur_h nonzeros, colsum partials -> bufA ----
    if (g < D) {
        g_inp[g] = sen[g];
        unsigned b = __ballot_sync(0xffffffffu, cur_h[g] != 0.f);
        if (lane == 0) g_hbits[wg] = b;        // always overwritten: deterministic
    }
    if (g == D) {
        int bits = pos_raw[0];
        g_inp[2 * D] = (bits >= 0 && bits < 1000000) ? (float)bits
                                                     : __int_as_float(bits);
    }
    for (int item = g; item < NP * DV; item += NTHR) {
        int chunk = item >> 9, c4 = item & 511;
        float4 w[16];
        #pragma unroll
        for (int r = 0; r < 16; ++r)
            w[r] = hid4[(size_t)(chunk * 16 + r) * DV + c4];
        float4 a = make_float4(0.f, 0.f, 0.f, 0.f);
        #pragma unroll
        for (int r = 0; r < 16; ++r) {
            a.x += w[r].x; a.y += w[r].y; a.z += w[r].z; a.w += w[r].w;
        }
        ((float4*)g_bufA)[item] = a;           // item == chunk*DV + c4
    }
    grid_bar();

    // ---- P1..P3: graph chain ----
    lmv_stage(g_bufA, dim_up4,   g_bufB, nullptr, 1.0f, 0, red, vsh);
    grid_bar();
    lmv_stage(g_bufB, W_gcn4,    g_bufA, cur_h, 1.0f / (float)N_NODES, 0, red, vsh);
    grid_bar();
    lmv_stage(g_bufA, dim_down4, g_bufB, nullptr, 1.0f, 1, red, vsh);
    grid_bar();

    // ---- P4: final reduce of dim_down partials -> g_inp[D : 2D); flag OR ----
    if (g == 0) {
        unsigned f = 0;
        #pragma unroll
        for (int i = 0; i < D / 32; ++i) f |= g_hbits[i];
        g_hflag = f;                           // always overwritten: deterministic
    }
    for (int c = wg; c < D; c += NWARP) {
        float a = 0.f;
        #pragma unroll
        for (int i = 0; i < 8; ++i)
            a += g_bufB[(lane + i * 32) * D + c];
        #pragma unroll
        for (int o = 16; o; o >>= 1) a += __shfl_down_sync(0xffffffffu, a, o);
        if (lane == 0) g_inp[D + c] = a;
    }
    grid_bar();

    // ---- P5: LSTM gate pre-activations, warp per (gate,row) ----
    // If cur_h is identically zero (the reference's initial state), Wh @ cur_h
    // is exactly zero: skip the 67 MB Wh stream. Guarded at runtime, so any
    // nonzero cur_h takes the full path (bit-identical to the unskipped code).
    {
        unsigned hnz = g_hflag;
        for (int row = wg; row < 4 * D; row += NWARP) {
            const float* wi_row = Wi + (size_t)row * INP;
            float acc = 0.f;
            #pragma unroll
            for (int b = 0; b < 8; ++b) {
                float w[16];
                int base = b * 512 + lane;
                #pragma unroll
                for (int j = 0; j < 16; ++j) w[j] = __ldg(wi_row + base + j * 32);
                #pragma unroll
                for (int j = 0; j < 16; ++j) acc += w[j] * g_inp[base + j * 32];
            }
            if (lane == 0) acc += wi_row[4096] * g_inp[4096];
            if (hnz) {
                const float4* wh_row = Wh4 + (size_t)row * DV;
                const float4* curh4  = (const float4*)cur_h;
                #pragma unroll
                for (int b = 0; b < 2; ++b) {
                    float4 w[8];
                    int base = b * 256 + lane;
                    #pragma unroll
                    for (int j = 0; j < 8; ++j) w[j] = __ldg(wh_row + base + j * 32);
                    #pragma unroll
                    for (int j = 0; j < 8; ++j) {
                        float4 h = __ldg(curh4 + base + j * 32);
                        acc += w[j].x * h.x + w[j].y * h.y + w[j].z * h.z + w[j].w * h.w;
                    }
                }
            }
            #pragma unroll
            for (int o = 16; o; o >>= 1) acc += __shfl_down_sync(0xffffffffu, acc, o);
            if (lane == 0) g_gsum[row] = acc + bi[row] + bh[row];
        }
    }
    grid_bar();

    // ---- P6: output matvec partials with fused LSTM gates ----
    for (int vt = blockIdx.x; vt < 512; vt += NBLK) {
        int kc = vt >> 5, nb = vt & 31;
        int k0 = kc * 128;
        __syncthreads();                       // guard vsh reuse across tiles
        if (t < 128) {
            int k = k0 + t;
            float i_g = sigf(g_gsum[k]);
            float f_g = sigf(g_gsum[D + k]);
            float g_g = tanhf(g_gsum[2 * D + k]);
            float o_g = sigf(g_gsum[3 * D + k]);
            float nc  = f_g * cur_cell[k] + i_g * g_g;
            vsh[t] = o_g * tanhf(nc);
        }
        __syncthreads();
        int n4 = nb * 256 + t;
        if (n4 < NTV) {
            float4 a = make_float4(0.f, 0.f, 0.f, 0.f);
            #pragma unroll 1
            for (int kb = 0; kb < 128; kb += 16) {
                float4 w[16];
                #pragma unroll
                for (int j = 0; j < 16; ++j)
                    w[j] = dim_out4[(size_t)(k0 + kb + j) * NTV + n4];
                #pragma unroll
                for (int j = 0; j < 16; ++j) {
                    float h = vsh[kb + j];
                    a.x += h * w[j].x; a.y += h * w[j].y;
                    a.z += h * w[j].z; a.w += h * w[j].w;
                }
            }
            ((float4*)g_pout)[kc * NTV + n4] = a;
        }
    }
    grid_bar();

    // ---- P7: output reduce ----
    for (int n4 = g; n4 < NTV; n4 += NTHR) {
        float4 a = make_float4(0.f, 0.f, 0.f, 0.f);
        #pragma unroll
        for (int k = 0; k < 16; ++k) {
            float4 v = ((const float4*)g_pout)[k * NTV + n4];
            a.x += v.x; a.y += v.y; a.z += v.z; a.w += v.w;
        }
        ((float4*)out)[n4] = a;
    }
}

// ---------------- launcher ----------------
// Inputs: 0 sen_emb [D], 1 hiddens [S,D], 2 pos_index [1], 3 dim_up [D,D],
// 4 dim_down [D,D], 5 dim_out [D,NT], 6 W_gcn [D,D], 7 att_w (unused; softmax
// over identical rows is exactly uniform), 8 Wi [4,D,INP], 9 Wh [4,D,D],
// 10 bi, 11 bh, 12 cur_h [D], 13 cur_cell [D]
extern "C" void kernel_launch(void* const* d_in, const int* in_sizes, int n_in,
                              void* d_out, int out_size) {
    const float* sen_emb  = (const float*)d_in[0];
    const float* hiddens  = (const float*)d_in[1];
    const int*   pos_raw  = (const int*)  d_in[2];
    const float* dim_up   = (const float*)d_in[3];
    const float* dim_down = (const float*)d_in[4];
    const float* dim_out  = (const float*)d_in[5];
    const float* W_gcn    = (const float*)d_in[6];
    const float* Wi       = (const float*)d_in[8];
    const float* Wh       = (const float*)d_in[9];
    const float* bi       = (const float*)d_in[10];
    const float* bh       = (const float*)d_in[11];
    const float* cur_h    = (const float*)d_in[12];
    const float* cur_cell = (const float*)d_in[13];
    float* out = (float*)d_out;

    k_mega<<<NBLK, 256>>>(
        sen_emb, pos_raw,
        (const float4*)hiddens,
        (const float4*)dim_up, (const float4*)W_gcn,
        (const float4*)dim_down, (const float4*)dim_out,
        Wi, (const float4*)Wh, bi, bh,
        cur_h, cur_cell, out);
}